// round 1
// baseline (speedup 1.0000x reference)
#include <cuda_runtime.h>

// Soft quantizer forward: out = hard nearest-level quantization.
// levels[k] = -1 + k * (2/24), k = 0..24.
// Straight-through estimator means forward value == hard_q exactly.

#define Z_MIN   (-1.0f)
#define STEP    (2.0f / 24.0f)      // (Z_MAX - Z_MIN) / (Z_LEVEL - 1)
#define INVSTEP (12.0f)             // 1 / STEP
#define LMAX    (24.0f)             // Z_LEVEL - 1

__device__ __forceinline__ float quant1(float x) {
    // index of nearest level, clamped
    float k = rintf((x - Z_MIN) * INVSTEP);
    k = fminf(fmaxf(k, 0.0f), LMAX);
    return fmaf(k, STEP, Z_MIN);
}

__global__ void __launch_bounds__(256) quant_kernel_v(const float4* __restrict__ in,
                                                      float4* __restrict__ out,
                                                      int n4) {
    // Each thread processes 2 float4 (8 floats) for MLP.
    int i0 = (blockIdx.x * blockDim.x + threadIdx.x) * 2;
    if (i0 + 1 < n4) {
        float4 a = in[i0];
        float4 b = in[i0 + 1];
        float4 ra, rb;
        ra.x = quant1(a.x); ra.y = quant1(a.y); ra.z = quant1(a.z); ra.w = quant1(a.w);
        rb.x = quant1(b.x); rb.y = quant1(b.y); rb.z = quant1(b.z); rb.w = quant1(b.w);
        out[i0]     = ra;
        out[i0 + 1] = rb;
    } else if (i0 < n4) {
        float4 a = in[i0];
        float4 ra;
        ra.x = quant1(a.x); ra.y = quant1(a.y); ra.z = quant1(a.z); ra.w = quant1(a.w);
        out[i0] = ra;
    }
}

__global__ void __launch_bounds__(256) quant_kernel_tail(const float* __restrict__ in,
                                                         float* __restrict__ out,
                                                         int start, int n) {
    int i = start + blockIdx.x * blockDim.x + threadIdx.x;
    if (i < n) out[i] = quant1(in[i]);
}

extern "C" void kernel_launch(void* const* d_in, const int* in_sizes, int n_in,
                              void* d_out, int out_size) {
    const float* x = (const float*)d_in[0];
    float* out = (float*)d_out;
    int n = in_sizes[0];

    int n4 = n / 4;               // full float4 chunks
    int tail_start = n4 * 4;

    if (n4 > 0) {
        // 2 float4 per thread
        int threads = 256;
        int items = (n4 + 1) / 2;                 // thread count needed
        int blocks = (items + threads - 1) / threads;
        quant_kernel_v<<<blocks, threads>>>((const float4*)x, (float4*)out, n4);
    }
    if (tail_start < n) {
        int rem = n - tail_start;
        int threads = 256;
        int blocks = (rem + threads - 1) / threads;
        quant_kernel_tail<<<blocks, threads>>>(x, out, tail_start, n);
    }
}

// round 3
// speedup vs baseline: 1.1084x; 1.1084x over previous
#include <cuda_runtime.h>

// Soft quantizer forward == hard nearest-level quantization (straight-through).
// levels[k] = -1 + k*(2/24), k = 0..24.

#define Z_MIN   (-1.0f)
#define STEP    (2.0f / 24.0f)
#define INVSTEP (12.0f)
#define LMAX    (24.0f)

__device__ __forceinline__ float quant1(float x) {
    float k = rintf((x - Z_MIN) * INVSTEP);
    k = fminf(fmaxf(k, 0.0f), LMAX);
    return fmaf(k, STEP, Z_MIN);
}

__device__ __forceinline__ float4 quant4(float4 a) {
    float4 r;
    r.x = quant1(a.x); r.y = quant1(a.y); r.z = quant1(a.z); r.w = quant1(a.w);
    return r;
}

// Block-tiled: each block covers blockDim.x * 4 consecutive float4s.
// Per-instruction lane stride = 16B -> fully coalesced LDG.128 (4 lines/warp/instr).
// 4 independent front-batched loads per thread (MLP_p1 = 4).
// Input: __ldcg (L2-cached, skip L1 — no intra-launch reuse).
// Output: __stcs (streaming / evict-first) so the 67MB output doesn't evict
// the 67MB input from the ~126MB L2 between graph replays.
__global__ void __launch_bounds__(256) quant_kernel_v4(const float4* __restrict__ in,
                                                       float4* __restrict__ out,
                                                       int n4) {
    int base = blockIdx.x * (blockDim.x * 4) + threadIdx.x;
    int s = blockDim.x;

    int i0 = base;
    int i1 = base + s;
    int i2 = base + 2 * s;
    int i3 = base + 3 * s;

    if (i3 < n4) {
        // fast path: all four in range (true for every block except possibly the last)
        float4 a = __ldcg(&in[i0]);
        float4 b = __ldcg(&in[i1]);
        float4 c = __ldcg(&in[i2]);
        float4 d = __ldcg(&in[i3]);
        __stcs(&out[i0], quant4(a));
        __stcs(&out[i1], quant4(b));
        __stcs(&out[i2], quant4(c));
        __stcs(&out[i3], quant4(d));
    } else {
        if (i0 < n4) __stcs(&out[i0], quant4(__ldcg(&in[i0])));
        if (i1 < n4) __stcs(&out[i1], quant4(__ldcg(&in[i1])));
        if (i2 < n4) __stcs(&out[i2], quant4(__ldcg(&in[i2])));
    }
}

__global__ void __launch_bounds__(256) quant_kernel_tail(const float* __restrict__ in,
                                                         float* __restrict__ out,
                                                         int start, int n) {
    int i = start + blockIdx.x * blockDim.x + threadIdx.x;
    if (i < n) out[i] = quant1(__ldcg(&in[i]));
}

extern "C" void kernel_launch(void* const* d_in, const int* in_sizes, int n_in,
                              void* d_out, int out_size) {
    const float* x = (const float*)d_in[0];
    float* out = (float*)d_out;
    int n = in_sizes[0];

    int n4 = n / 4;
    int tail_start = n4 * 4;

    if (n4 > 0) {
        const int threads = 256;
        const int per_block = threads * 4;                 // float4s per block
        int blocks = (n4 + per_block - 1) / per_block;
        quant_kernel_v4<<<blocks, threads>>>((const float4*)x, (float4*)out, n4);
    }
    if (tail_start < n) {
        int rem = n - tail_start;
        int threads = 256;
        int blocks = (rem + threads - 1) / threads;
        quant_kernel_tail<<<blocks, threads>>>(x, out, tail_start, n);
    }
}